// round 17
// baseline (speedup 1.0000x reference)
#include <cuda_runtime.h>
#include <cuda_fp16.h>
#include <cstdint>

// Problem dims
#define NN 8192      // nodes
#define EE 16384     // edges
#define GG 512       // graphs
#define IND 235      // input dim
#define HD 64        // hidden
#define EDIM 52      // edge feature dim
#define KP 240       // padded K (15 k-tiles of 16)
#define JB 3456      // U columns: 3328 (d*64+h) + 64 (c0) + 64 (root)
#define MROWS 15040  // IN*H
#define NKT 15       // k-tiles
#define NSPLIT 2304  // cols [0,2304) -> HMMA path; [2304,3456) -> FFMA path

typedef unsigned long long ull;

// ---------------- scratch (device globals; no allocation allowed) ----------
__device__ __half g_A[NN * KP];            // 3.9 MB  fp16 A, fragment-ordered
__device__ float  g_Xf[NN * KP];           // 7.9 MB  fp32 A, [mblk][kt][k16][m128]
__device__ __half g_B[NSPLIT * KP];        // 1.1 MB  fp16 B cols<2304, fragment-ordered
__device__ float  g_Bf[(JB - NSPLIT) * KP];// 1.1 MB  fp32 B cols>=2304, [nblk][kt][k16][n128]
__device__ __half g_Uh[NN * JB];           // 56.6 MB U (fp16)
__device__ float  g_agg[NN * HD];
__device__ float  g_pool[GG * HD];
__device__ int    g_cnt[GG];

// ---------------- index helpers --------------------------------------------
// fp16 A fragment layout (see R16): within (mblk,kt) region of 2048 halves
__device__ __forceinline__ int aidx_h(int n, int i) {
    int mblk = n >> 7, ml = n & 127;
    int wgrp = ml >> 6, mlo = ml & 63;
    int mt = mlo >> 4, r16 = mlo & 15;
    int gid = r16 & 7, rhalf = r16 >> 3;
    int kt = i >> 4, kl = i & 15;
    int khalf = kl >> 3, k7 = kl & 7;
    int tig = k7 >> 1, lohi = k7 & 1;
    return ((mblk * NKT + kt) << 11) + (wgrp << 10) + (mt << 8)
         + ((gid * 4 + tig) << 3) + ((khalf * 2 + rhalf) << 1) + lohi;
}
// fp16 B fragment layout (256-wide blocks)
__device__ __forceinline__ int bidx_h(int n, int i) {
    int nblk = n >> 8, nl = n & 255;
    int wgrp = nl >> 6, n64 = nl & 63;
    int nt = n64 >> 3, gid = n64 & 7;
    int kt = i >> 4, kl = i & 15;
    int khalf = kl >> 3, k7 = kl & 7;
    int tig = k7 >> 1, lohi = k7 & 1;
    return ((nblk * NKT + kt) << 12) + (wgrp << 10) + ((nt >> 1) << 8)
         + ((gid * 4 + tig) << 3) + ((nt & 1) << 2) + (khalf << 1) + lohi;
}
// fp32 A layout: [mblk][kt][k16][m128]
__device__ __forceinline__ int afidx(int n, int i) {
    return (((n >> 7) * NKT + (i >> 4)) << 11) + ((i & 15) << 7) + (n & 127);
}
// fp32 B layout (cols >= NSPLIT): [nblk128][kt][k16][n128]
__device__ __forceinline__ int bfidx(int n, int i) {
    int nf = n - NSPLIT;
    return (((nf >> 7) * NKT + (i >> 4)) << 11) + ((i & 15) << 7) + (nf & 127);
}
__device__ __forceinline__ void mma_f16(float* c, unsigned a0, unsigned a1,
                                        unsigned a2, unsigned a3,
                                        unsigned b0, unsigned b1) {
    asm volatile(
        "mma.sync.aligned.m16n8k16.row.col.f32.f16.f16.f32 "
        "{%0,%1,%2,%3}, {%4,%5,%6,%7}, {%8,%9}, {%0,%1,%2,%3};"
        : "+f"(c[0]), "+f"(c[1]), "+f"(c[2]), "+f"(c[3])
        : "r"(a0), "r"(a1), "r"(a2), "r"(a3), "r"(b0), "r"(b1));
}
__device__ __forceinline__ void cp16(unsigned saddr, const void* g) {
    asm volatile("cp.async.cg.shared.global [%0], [%1], 16;"
                 :: "r"(saddr), "l"(g) : "memory");
}
__device__ __forceinline__ ull ffma2(ull a, ull b, ull c) {
    ull d;
    asm("fma.rn.f32x2 %0, %1, %2, %3;" : "=l"(d) : "l"(a), "l"(b), "l"(c));
    return d;
}
__device__ __forceinline__ ull pack2(float lo, float hi) {
    ull r;
    asm("mov.b64 %0, {%1, %2};" : "=l"(r) : "f"(lo), "f"(hi));
    return r;
}
__device__ __forceinline__ float2 unpack2(ull v) {
    float2 r;
    asm("mov.b64 {%0, %1}, %2;" : "=f"(r.x), "=f"(r.y) : "l"(v));
    return r;
}

// ---------------- prep: physical-order fills --------------------------------
__global__ void prep_kernel(const float* __restrict__ x,
                            const float* __restrict__ root) {
    const int S1 = NN * KP;              // g_A halves (physical order)
    const int S2 = NN * KP;              // g_Xf floats (physical order)
    const int NZ1 = NN * HD, NZ2 = GG * HD, NZ3 = GG;
    const int NR = IND * HD;             // root -> g_Bf
    const int NB = JB * (KP - IND);      // B k-pad zeros
    const int total = S1 + S2 + NZ1 + NZ2 + NZ3 + NR + NB;
    for (int idx = blockIdx.x * blockDim.x + threadIdx.x; idx < total;
         idx += gridDim.x * blockDim.x) {
        int t = idx;
        if (t < S1) {  // g_A physical order: coalesced half stores
            int r = t >> 11, w = t & 2047;
            int mblk = r / NKT, kt = r - mblk * NKT;
            int wgrp = w >> 10, mt = (w >> 8) & 3, q = (w >> 3) & 31;
            int gid = q >> 2, tig = q & 3;
            int khalf = (w >> 2) & 1, rhalf = (w >> 1) & 1, lohi = w & 1;
            int n = mblk * 128 + wgrp * 64 + mt * 16 + rhalf * 8 + gid;
            int i = kt * 16 + khalf * 8 + tig * 2 + lohi;
            g_A[t] = __float2half_rn((i < IND) ? x[n * IND + i] : 0.0f);
            continue;
        }
        t -= S1;
        if (t < S2) {  // g_Xf physical order: coalesced float stores
            int r = t >> 11, w = t & 2047;
            int mblk = r / NKT, kt = r - mblk * NKT;
            int kl = w >> 7, ml = w & 127;
            int n = mblk * 128 + ml, i = kt * 16 + kl;
            g_Xf[t] = (i < IND) ? x[n * IND + i] : 0.0f;
            continue;
        }
        t -= S2;
        if (t < NZ1) { g_agg[t] = 0.0f; continue; }
        t -= NZ1;
        if (t < NZ2) { g_pool[t] = 0.0f; continue; }
        t -= NZ2;
        if (t < NZ3) { g_cnt[t] = 0; continue; }
        t -= NZ3;
        if (t < NR) {
            int i = t >> 6, h = t & 63;
            g_Bf[bfidx(3392 + h, i)] = root[t];
            continue;
        }
        t -= NR;
        {
            int n = t / (KP - IND), i = IND + (t - n * (KP - IND));
            if (n < NSPLIT) g_B[bidx_h(n, i)] = __float2half_rn(0.0f);
            else            g_Bf[bfidx(n, i)] = 0.0f;
        }
    }
}

// ---------------- build C = W2 @ W1 and c0 ----------------------------------
__global__ void buildC_kernel(const float* __restrict__ W1,
                              const float* __restrict__ b1,
                              const float* __restrict__ W2,
                              const float* __restrict__ b2) {
    int m = (blockIdx.x * blockDim.x + threadIdx.x) >> 5;
    int lane = threadIdx.x & 31;
    if (m >= MROWS) return;
    const float* w2row = W2 + m * 128;
    int d0 = lane, d1 = lane + 32;
    float acc0 = 0.f, acc1 = 0.f, accb = 0.f;
#pragma unroll 4
    for (int k = 0; k < 128; ++k) {
        float w2 = __ldg(w2row + k);
        float w1a = __ldg(W1 + k * EDIM + d0);
        float w1b = (d1 < EDIM) ? __ldg(W1 + k * EDIM + d1) : 0.0f;
        acc0 = fmaf(w2, w1a, acc0);
        acc1 = fmaf(w2, w1b, acc1);
        accb = fmaf(w2, __ldg(b1 + k), accb);
    }
    int i = m >> 6, h = m & 63;
    int n0c = d0 * 64 + h;
    if (n0c < NSPLIT) g_B[bidx_h(n0c, i)] = __float2half_rn(acc0);
    else              g_Bf[bfidx(n0c, i)] = acc0;
    if (d1 < EDIM) {
        int n1c = d1 * 64 + h;    // always >= 2048+h; d1>=32 -> n1c>=2048; d1>=36 -> >=2304
        if (n1c < NSPLIT) g_B[bidx_h(n1c, i)] = __float2half_rn(acc1);
        else              g_Bf[bfidx(n1c, i)] = acc1;
    }
    if (lane == 0) g_Bf[bfidx(3328 + h, i)] = accb + b2[m];
}

// ---------------- hybrid GEMM: HMMA CTAs + FFMA CTAs in one grid ------------
// grid = (18, 64).  bx<9: fp16 HMMA, 256-col tile.  bx>=9: f32x2 FFMA, 128-col.
#define AT_H 2048
#define BT_H 4096
#define BUF_B 12288     // HMMA double-buffer stride (bytes)
#define FBUF 4096       // FFMA buffer stride (floats): 2048 A + 2048 B

__global__ void __launch_bounds__(256, 1)
gemm_kernel() {
    __shared__ __align__(16) char smraw[32768];

    const int tid  = threadIdx.x;
    const int lane = tid & 31;
    const int warp = tid >> 5;
    const int m0   = blockIdx.y * 128;

    if (blockIdx.x < 9) {
        // =================== HMMA path (cols 0..2303) =======================
        __half* smem = (__half*)smraw;
        const int gid = lane >> 2, tig = lane & 3;
        const int n0  = blockIdx.x * 256;
        const int wgA = warp >> 2;
        const int wgB = warp & 3;

        const unsigned sbase = (unsigned)__cvta_generic_to_shared(smem);
        const __half* gAt = g_A + (size_t)blockIdx.y * (NKT * AT_H);
        const __half* gBt = g_B + (size_t)blockIdx.x * (NKT * BT_H);

        float acc[4][8][4];
#pragma unroll
        for (int mt = 0; mt < 4; ++mt)
#pragma unroll
            for (int nt = 0; nt < 8; ++nt)
#pragma unroll
                for (int i = 0; i < 4; ++i) acc[mt][nt][i] = 0.0f;

        {
            unsigned sA = sbase, sB = sbase + AT_H * 2;
            cp16(sA + tid * 16, gAt + tid * 8);
            cp16(sB + tid * 16, gBt + tid * 8);
            cp16(sB + (tid + 256) * 16, gBt + (tid + 256) * 8);
            asm volatile("cp.async.commit_group;" ::: "memory");
        }

#pragma unroll 1
        for (int kt = 0; kt < NKT; ++kt) {
            if (kt < NKT - 1) {
                const int nb = (kt + 1) & 1;
                unsigned sA = sbase + nb * BUF_B, sB = sA + AT_H * 2;
                const __half* ga = gAt + (kt + 1) * AT_H;
                const __half* gb = gBt + (kt + 1) * BT_H;
                cp16(sA + tid * 16, ga + tid * 8);
                cp16(sB + tid * 16, gb + tid * 8);
                cp16(sB + (tid + 256) * 16, gb + (tid + 256) * 8);
                asm volatile("cp.async.commit_group;" ::: "memory");
                asm volatile("cp.async.wait_group 1;" ::: "memory");
            } else {
                asm volatile("cp.async.wait_group 0;" ::: "memory");
            }
            __syncthreads();

            const __half* sA = smem + (kt & 1) * (AT_H + BT_H);
            const __half* sB = sA + AT_H;

            uint4 Af[4], Bf[4];
#pragma unroll
            for (int mt = 0; mt < 4; ++mt)
                Af[mt] = *(const uint4*)(sA + (wgA << 10) + (mt << 8) + lane * 8);
#pragma unroll
            for (int c = 0; c < 4; ++c)
                Bf[c] = *(const uint4*)(sB + (wgB << 10) + (c << 8) + lane * 8);

#pragma unroll
            for (int c = 0; c < 4; ++c) {
#pragma unroll
                for (int mt = 0; mt < 4; ++mt)
                    mma_f16(acc[mt][2 * c], Af[mt].x, Af[mt].y, Af[mt].z, Af[mt].w,
                            Bf[c].x, Bf[c].y);
#pragma unroll
                for (int mt = 0; mt < 4; ++mt)
                    mma_f16(acc[mt][2 * c + 1], Af[mt].x, Af[mt].y, Af[mt].z, Af[mt].w,
                            Bf[c].z, Bf[c].w);
            }
            __syncthreads();
        }

        const int wn = wgB * 64;
#pragma unroll
        for (int mt = 0; mt < 4; ++mt) {
            int grow = m0 + wgA * 64 + mt * 16 + gid;
            __half* base = g_Uh + (size_t)grow * JB + n0 + wn + 2 * tig;
#pragma unroll
            for (int nt = 0; nt < 8; ++nt) {
                __half* p = base + nt * 8;
                *(__half2*)p            = __float22half2_rn(make_float2(acc[mt][nt][0], acc[mt][nt][1]));
                *(__half2*)(p + 8 * JB) = __float22half2_rn(make_float2(acc[mt][nt][2], acc[mt][nt][3]));
            }
        }
    } else {
        // =================== FFMA path (cols 2304..3455) ====================
        float* fsm = (float*)smraw;
        const int bxf = blockIdx.x - 9;
        const int n0  = NSPLIT + bxf * 128;
        const int tm0 = (tid >> 4) * 8;
        const int tn0 = (tid & 15) * 8;

        const unsigned sbase = (unsigned)__cvta_generic_to_shared(fsm);
        const float* gAt = g_Xf + (size_t)blockIdx.y * (NKT * 2048);
        const float* gBt = g_Bf + (size_t)bxf * (NKT * 2048);

        ull acc[8][4];
#pragma unroll
        for (int mm = 0; mm < 8; ++mm)
#pragma unroll
            for (int nn = 0; nn < 4; ++nn) acc[mm][nn] = 0ULL;

        {
            unsigned sA = sbase, sB = sbase + 2048 * 4;
            cp16(sA + tid * 16, gAt + tid * 4);
            cp16(sA + (tid + 256) * 16, gAt + (tid + 256) * 4);
            cp16(sB + tid * 16, gBt + tid * 4);
            cp16(sB + (tid + 256) * 16, gBt + (tid + 256) * 4);
            asm volatile("cp.async.commit_group;" ::: "memory");
        }

#pragma unroll 1
        for (int kt = 0; kt < NKT; ++kt) {
            if (kt < NKT - 1) {
                const int nb = (kt + 1) & 1;
                unsigned sA = sbase + nb * (FBUF * 4), sB = sA + 2048 * 4;
                const float* ga = gAt + (kt + 1) * 2048;
                const float* gb = gBt + (kt + 1) * 2048;
                cp16(sA + tid * 16, ga + tid * 4);
                cp16(sA + (tid + 256) * 16, ga + (tid + 256) * 4);
                cp16(sB + tid * 16, gb + tid * 4);
                cp16(sB + (tid + 256) * 16, gb + (tid + 256) * 4);
                asm volatile("cp.async.commit_group;" ::: "memory");
                asm volatile("cp.async.wait_group 1;" ::: "memory");
            } else {
                asm volatile("cp.async.wait_group 0;" ::: "memory");
            }
            __syncthreads();

            const float* As = fsm + (kt & 1) * FBUF;
            const float* Bs = As + 2048;

#pragma unroll
            for (int k = 0; k < 16; ++k) {
                float4 a0 = *(const float4*)(As + k * 128 + tm0);
                float4 a1 = *(const float4*)(As + k * 128 + tm0 + 4);
                float4 bv0 = *(const float4*)(Bs + k * 128 + tn0);
                float4 bv1 = *(const float4*)(Bs + k * 128 + tn0 + 4);
                ull b0 = pack2(bv0.x, bv0.y);
                ull b1 = pack2(bv0.z, bv0.w);
                ull b2 = pack2(bv1.x, bv1.y);
                ull b3 = pack2(bv1.z, bv1.w);
                float am[8] = {a0.x, a0.y, a0.z, a0.w, a1.x, a1.y, a1.z, a1.w};
#pragma unroll
                for (int mm = 0; mm < 8; ++mm) {
                    ull ad = pack2(am[mm], am[mm]);
                    acc[mm][0] = ffma2(ad, b0, acc[mm][0]);
                    acc[mm][1] = ffma2(ad, b1, acc[mm][1]);
                    acc[mm][2] = ffma2(ad, b2, acc[mm][2]);
                    acc[mm][3] = ffma2(ad, b3, acc[mm][3]);
                }
            }
            __syncthreads();
        }

#pragma unroll
        for (int mm = 0; mm < 8; ++mm) {
            __half* p = g_Uh + (size_t)(m0 + tm0 + mm) * JB + n0 + tn0;
            float2 p0 = unpack2(acc[mm][0]);
            float2 p1 = unpack2(acc[mm][1]);
            float2 p2 = unpack2(acc[mm][2]);
            float2 p3 = unpack2(acc[mm][3]);
            __half2 h0 = __float22half2_rn(p0);
            __half2 h1 = __float22half2_rn(p1);
            __half2 h2 = __float22half2_rn(p2);
            __half2 h3 = __float22half2_rn(p3);
            uint4 v;
            v.x = *(unsigned*)&h0; v.y = *(unsigned*)&h1;
            v.z = *(unsigned*)&h2; v.w = *(unsigned*)&h3;
            *(uint4*)p = v;
        }
    }
}

// ---------------- edge kernel: gather U[src], contract ea, scatter to agg --
__global__ void edge_kernel(const int* __restrict__ ei,
                            const float* __restrict__ ea) {
    int e = (blockIdx.x * blockDim.x + threadIdx.x) >> 5;
    int lane = threadIdx.x & 31;
    if (e >= EE) return;
    int src = ei[e];
    int dst = ei[EE + e];
    const __half* urow = g_Uh + (size_t)src * JB;
    const float* earow = ea + e * EDIM;

    float2 acc = __half22float2(*(const __half2*)(urow + 3328 + 2 * lane));
#pragma unroll 4
    for (int d = 0; d < EDIM; ++d) {
        float ed = __ldg(earow + d);
        float2 u = __half22float2(*(const __half2*)(urow + d * 64 + 2 * lane));
        acc.x = fmaf(ed, u.x, acc.x);
        acc.y = fmaf(ed, u.y, acc.y);
    }
    atomicAdd(&g_agg[dst * 64 + 2 * lane],     acc.x);
    atomicAdd(&g_agg[dst * 64 + 2 * lane + 1], acc.y);
}

// ---------------- node kernel: relu(agg + x@root + b), pool scatter --------
__global__ void node_kernel(const int* __restrict__ batch,
                            const float* __restrict__ conv_b) {
    int n = (blockIdx.x * blockDim.x + threadIdx.x) >> 5;
    int lane = threadIdx.x & 31;
    if (n >= NN) return;
    float2 a  = *(const float2*)&g_agg[n * 64 + 2 * lane];
    float2 xr = __half22float2(*(const __half2*)(g_Uh + (size_t)n * JB + 3392 + 2 * lane));
    float ox = fmaxf(a.x + xr.x + __ldg(conv_b + 2 * lane),     0.0f);
    float oy = fmaxf(a.y + xr.y + __ldg(conv_b + 2 * lane + 1), 0.0f);
    int g = batch[n];
    atomicAdd(&g_pool[g * 64 + 2 * lane],     ox);
    atomicAdd(&g_pool[g * 64 + 2 * lane + 1], oy);
    if (lane == 0) atomicAdd(&g_cnt[g], 1);
}

// ---------------- fused MLP head: block per graph --------------------------
__global__ void mlp_kernel(const float* __restrict__ fw1, const float* __restrict__ fb1,
                           const float* __restrict__ fw2, const float* __restrict__ fb2,
                           const float* __restrict__ fw3, const float* __restrict__ fb3,
                           const float* __restrict__ fw4, const float* __restrict__ fb4,
                           float* __restrict__ out) {
    int g = blockIdx.x;
    int t = threadIdx.x;
    __shared__ float s0[64], s1[128], s2[256], s3[128];

    if (t < 64) {
        float c = fmaxf((float)g_cnt[g], 1.0f);
        s0[t] = g_pool[g * 64 + t] / c;
    }
    __syncthreads();

    if (t < 128) {
        float a = fb1[t];
#pragma unroll 8
        for (int j = 0; j < 64; ++j) a = fmaf(__ldg(fw1 + t * 64 + j), s0[j], a);
        s1[t] = fmaxf(a, 0.0f);
    }
    __syncthreads();

    {
        float a = fb2[t];
#pragma unroll 8
        for (int j = 0; j < 128; ++j) a = fmaf(__ldg(fw2 + t * 128 + j), s1[j], a);
        s2[t] = fmaxf(a, 0.0f);
    }
    __syncthreads();

    if (t < 128) {
        float a = fb3[t];
#pragma unroll 8
        for (int j = 0; j < 256; ++j) a = fmaf(__ldg(fw3 + t * 256 + j), s2[j], a);
        s3[t] = fmaxf(a, 0.0f);
    }
    __syncthreads();

    if (t < 32) {
        float a = 0.0f;
        for (int j = t; j < 128; j += 32) a = fmaf(__ldg(fw4 + j), s3[j], a);
#pragma unroll
        for (int o = 16; o; o >>= 1) a += __shfl_down_sync(0xffffffffu, a, o);
        if (t == 0) out[g] = a + fb4[0];
    }
}

// ---------------- launcher -------------------------------------------------
extern "C" void kernel_launch(void* const* d_in, const int* in_sizes, int n_in,
                              void* d_out, int out_size) {
    const float* x      = (const float*)d_in[0];
    const int*   ei     = (const int*)  d_in[1];
    const float* ea     = (const float*)d_in[2];
    const int*   batch  = (const int*)  d_in[3];
    const float* W1     = (const float*)d_in[4];
    const float* b1     = (const float*)d_in[5];
    const float* W2     = (const float*)d_in[6];
    const float* b2     = (const float*)d_in[7];
    const float* root   = (const float*)d_in[8];
    const float* conv_b = (const float*)d_in[9];
    const float* fw1    = (const float*)d_in[10];
    const float* fb1    = (const float*)d_in[11];
    const float* fw2    = (const float*)d_in[12];
    const float* fb2    = (const float*)d_in[13];
    const float* fw3    = (const float*)d_in[14];
    const float* fb3    = (const float*)d_in[15];
    const float* fw4    = (const float*)d_in[16];
    const float* fb4    = (const float*)d_in[17];
    float* out = (float*)d_out;

    prep_kernel<<<4096, 256>>>(x, root);
    buildC_kernel<<<(MROWS + 7) / 8, 256>>>(W1, b1, W2, b2);
    gemm_kernel<<<dim3(18, NN / 128), 256>>>();
    edge_kernel<<<EE / 8, 256>>>(ei, ea);
    node_kernel<<<NN / 8, 256>>>(batch, conv_b);
    mlp_kernel<<<GG, 256>>>(fw1, fb1, fw2, fb2, fw3, fb3, fw4, fb4, out);
}